// round 2
// baseline (speedup 1.0000x reference)
#include <cuda_runtime.h>
#include <cstdint>

// Packed fp32x2 FMA (Blackwell): 2x FFMA throughput, only reachable via PTX.
#define FMA2(d, a, b, c) \
    asm("fma.rn.f32x2 %0, %1, %2, %3;" : "=l"(d) : "l"(a), "l"(b), "l"(c))
#define MUL2(d, a, b) \
    asm("mul.rn.f32x2 %0, %1, %2;" : "=l"(d) : "l"(a), "l"(b))

__device__ __forceinline__ unsigned long long pack2(float lo, float hi) {
    unsigned long long r;
    asm("mov.b64 %0, {%1, %2};" : "=l"(r) : "f"(lo), "f"(hi));
    return r;
}
__device__ __forceinline__ void unpack2(unsigned long long p, float& lo, float& hi) {
    asm("mov.b64 {%0, %1}, %2;" : "=f"(lo), "=f"(hi) : "l"(p));
}
__device__ __forceinline__ float ex2f(float x) {
    float r;
    asm("ex2.approx.ftz.f32 %0, %1;" : "=f"(r) : "f"(x));
    return r;
}
// 16B shared load delivering two packed f32x2 (avoids pack MOVs).
__device__ __forceinline__ void lds_v2u64(unsigned long long& a, unsigned long long& b,
                                          uint32_t saddr) {
    asm volatile("ld.shared.v2.u64 {%0, %1}, [%2];" : "=l"(a), "=l"(b) : "r"(saddr));
}

static constexpr int D       = 64;
static constexpr int S       = 8192;
static constexpr int G       = 32;    // N_GLOBAL
static constexpr int OUTROWS = 7936;  // S - WINDOW/2
static constexpr int TQ      = 128;   // queries per CTA
static constexpr int TK      = 16;    // keys per smem tile
static constexpr int NTHREADS = 256;

__global__ __launch_bounds__(NTHREADS, 2)
void swa_kernel(const float* __restrict__ qg, const float* __restrict__ kg,
                const float* __restrict__ vg, float* __restrict__ outg)
{
    __shared__ float kbuf[TK * D];   // 4 KB
    __shared__ float vbuf[TK * D];   // 4 KB

    const int bh = blockIdx.y;
    const int qb = blockIdx.x;

    // Key range for this query block.
    int kstart, klen;
    if (qb < 2) { kstart = 0; klen = 256; }                 // first half-window block
    else { int c = (qb - 2) >> 2; kstart = 256 + 512 * c; klen = 512; }
    const int ntiles = 2 + klen / TK;   // 2 global tiles (rows 0..31) + local tiles

    const int tid  = threadIdx.x;
    const int w    = tid >> 5;
    const int lane = tid & 31;
    const int qrow = qb * TQ + w * 16 + (lane >> 1); // this thread's query row
    const int half = lane & 1;                        // which 32 dims of D=64

    // Fold 1/sqrt(D) * log2(e) into Q.
    const float SC = 0.125f * 1.44269504088896340736f;

    // Q in registers, packed f32x2: 16 x u64 = 32 floats.
    unsigned long long q2[16];
    {
        const float4* qp = (const float4*)(qg + ((size_t)bh * S + qrow) * D + half * 32);
        #pragma unroll
        for (int i = 0; i < 8; i++) {
            float4 t = qp[i];
            q2[2 * i]     = pack2(t.x * SC, t.y * SC);
            q2[2 * i + 1] = pack2(t.z * SC, t.w * SC);
        }
    }

    unsigned long long o2[16];
    #pragma unroll
    for (int i = 0; i < 16; i++) o2[i] = 0ull;
    float m = -1e30f, l = 0.f;

    const uint32_t ksm = (uint32_t)__cvta_generic_to_shared(kbuf);
    const uint32_t vsm = (uint32_t)__cvta_generic_to_shared(vbuf);
    const uint32_t hoff = (uint32_t)(half * 32 * 4);  // byte offset of this thread's half

    for (int t = 0; t < ntiles; t++) {
        const int krow = (t < 2) ? t * TK : kstart + (t - 2) * TK;

        // Cooperative tile load: 256 float4 per buffer, one per thread.
        {
            const int r = tid >> 4, c4 = tid & 15;
            const size_t gofs = ((size_t)bh * S + krow + r) * D + c4 * 4;
            ((float4*)kbuf)[tid] = *(const float4*)(kg + gofs);
            ((float4*)vbuf)[tid] = *(const float4*)(vg + gofs);
        }
        __syncthreads();

        // ---- scores: s[j] = (q . k_j) * scale * log2e ----
        float sarr[TK];
        #pragma unroll
        for (int j = 0; j < TK; j++) {
            unsigned long long acc = 0ull;
            const uint32_t base = ksm + (uint32_t)(j * D * 4) + hoff;
            #pragma unroll
            for (int i = 0; i < 8; i++) {
                unsigned long long k0, k1;
                lds_v2u64(k0, k1, base + i * 16);
                FMA2(acc, q2[2 * i],     k0, acc);
                FMA2(acc, q2[2 * i + 1], k1, acc);
            }
            float lo, hi;
            unpack2(acc, lo, hi);
            float s = lo + hi;
            s += __shfl_xor_sync(0xffffffffu, s, 1);  // combine the two halves
            sarr[j] = s;
        }

        // ---- online softmax (log2 domain) ----
        float tmax = sarr[0];
        #pragma unroll
        for (int j = 1; j < TK; j++) tmax = fmaxf(tmax, sarr[j]);
        const float mnew  = fmaxf(m, tmax);
        const float alpha = ex2f(m - mnew);
        m = mnew;
        l *= alpha;
        const unsigned long long a2 = pack2(alpha, alpha);
        #pragma unroll
        for (int i = 0; i < 16; i++) MUL2(o2[i], o2[i], a2);
        #pragma unroll
        for (int j = 0; j < TK; j++) {
            sarr[j] = ex2f(sarr[j] - mnew);   // reuse sarr as p[]
            l += sarr[j];
        }

        // ---- O += P V ----
        #pragma unroll
        for (int j = 0; j < TK; j++) {
            const unsigned long long p2 = pack2(sarr[j], sarr[j]);
            const uint32_t base = vsm + (uint32_t)(j * D * 4) + hoff;
            #pragma unroll
            for (int i = 0; i < 8; i++) {
                unsigned long long v0, v1;
                lds_v2u64(v0, v1, base + i * 16);
                FMA2(o2[2 * i],     p2, v0, o2[2 * i]);
                FMA2(o2[2 * i + 1], p2, v1, o2[2 * i + 1]);
            }
        }
        __syncthreads();
    }

    // ---- normalize + store ----
    const float inv = 1.f / l;
    const unsigned long long inv2 = pack2(inv, inv);
    float4* op = (float4*)(outg + ((size_t)bh * OUTROWS + qrow) * D + half * 32);
    #pragma unroll
    for (int i = 0; i < 8; i++) {
        unsigned long long r0, r1;
        MUL2(r0, o2[2 * i],     inv2);
        MUL2(r1, o2[2 * i + 1], inv2);
        float4 o4;
        unpack2(r0, o4.x, o4.y);
        unpack2(r1, o4.z, o4.w);
        op[i] = o4;
    }
}

extern "C" void kernel_launch(void* const* d_in, const int* in_sizes, int n_in,
                              void* d_out, int out_size)
{
    const float* q = (const float*)d_in[0];
    const float* k = (const float*)d_in[1];
    const float* v = (const float*)d_in[2];
    float* out = (float*)d_out;

    // 62 query-blocks of 128 rows per (b,h): 2 for the first 256 rows,
    // then 4 per 512-row chunk x 15 chunks. 32 = B*H.
    dim3 grid(62, 32);
    swa_kernel<<<grid, NTHREADS>>>(q, k, v, out);
}